// round 11
// baseline (speedup 1.0000x reference)
#include <cuda_runtime.h>
#include <cstdint>

// Problem constants (fixed by the reference)
#define B_ 16
#define H_ 100
#define W_ 100
#define C_ 256
#define R_ 128
#define P_ 7
#define CELLS (P_ * P_)   // 49
#define NW 8              // warps per CTA
#define DEPTH 2           // pipeline slots per warp
#define SLOT_BYTES (4 * 512)   // 4 corners x 512B (channel half)

__device__ __forceinline__ float4 lerp4(float4 a, float4 b, float4 c, float4 d,
                                        float fx, float fy)
{
    float4 o;
    float top, bot;
    top = a.x + (b.x - a.x) * fx;  bot = c.x + (d.x - c.x) * fx;  o.x = top + (bot - top) * fy;
    top = a.y + (b.y - a.y) * fx;  bot = c.y + (d.y - c.y) * fx;  o.y = top + (bot - top) * fy;
    top = a.z + (b.z - a.z) * fx;  bot = c.z + (d.z - c.z) * fx;  o.z = top + (bot - top) * fy;
    top = a.w + (b.w - a.w) * fx;  bot = c.w + (d.w - c.w) * fx;  o.w = top + (bot - top) * fy;
    return o;
}

__device__ __forceinline__ void cp16(uint32_t smem_addr, const void* gptr)
{
    asm volatile("cp.async.cg.shared.global [%0], [%1], 16;"
                 :: "r"(smem_addr), "l"(gptr));
}

// TWO CTAs per ROI (channel halves), grid = 4096, 256 threads = 8 warps.
// Each warp is one cell-lane (32 channel threads x 16B = its 512B half-row per
// corner). Corner data is staged GMEM -> SMEM via cp.async.cg with a per-warp
// double buffer: while cell k is computed from SMEM (LDS.128, 29cyc), cell k+1
// is in flight. cp.async has no register target, so in-flight data costs zero
// registers/occupancy — this is the lever the LDG variants (R3-R10, all ~35us)
// could not reach: ILP there traded 1:1 against occupancy.
// Each thread reads back exactly the 16B it fetched, so wait_group alone
// orders the pipeline (no __syncwarp needed).
__global__ __launch_bounds__(256) void roi_pool_kernel(
    const float* __restrict__ fm,   // [B, H, W, C]
    const int*   __restrict__ rois, // [B, R, 4]  (x, y, h, w)
    float*       __restrict__ out)  // [B, R, P, P, C]
{
    __shared__ int4   s_off[CELLS];   // float4-unit offsets of the 4 corners
    __shared__ float2 s_fr[CELLS];    // (fx, fy)
    __shared__ __align__(16) char s_buf[NW * DEPTH * SLOT_BYTES];  // 32 KB

    const int roi_idx = blockIdx.x >> 1;        // b*R + r
    const int chalf   = blockIdx.x & 1;         // channel half 0/1
    const int b = roi_idx >> 7;                 // R_ = 128
    const int tid = threadIdx.x;

    if (tid < CELLS) {
        const int4 roi = __ldg((const int4*)(rois + (size_t)roi_idx * 4));
        const int x = roi.x, y = roi.y, h = roi.z, w = roi.w;

        const int py = tid / P_;
        const int px = tid - py * P_;

        // y axis: src = (py+0.5)/P * h - 0.5, clipped to [0, h-1]
        const float hf = (float)h;
        float sy = ((float)py + 0.5f) * (1.0f / P_) * hf - 0.5f;
        sy = fminf(fmaxf(sy, 0.0f), hf - 1.0f);
        int   y0 = (int)floorf(sy);
        const float fy = sy - (float)y0;
        y0 += y;
        const int y1 = min(y0 + 1, y + h - 1);

        // x axis
        const float wf = (float)w;
        float sx = ((float)px + 0.5f) * (1.0f / P_) * wf - 0.5f;
        sx = fminf(fmaxf(sx, 0.0f), wf - 1.0f);
        int   x0 = (int)floorf(sx);
        const float fx = sx - (float)x0;
        x0 += x;
        const int x1 = min(x0 + 1, x + w - 1);

        // offsets in float4 units (C_/4 = 64 per pixel row)
        s_off[tid] = make_int4((y0 * W_ + x0) * (C_ / 4),
                               (y0 * W_ + x1) * (C_ / 4),
                               (y1 * W_ + x0) * (C_ / 4),
                               (y1 * W_ + x1) * (C_ / 4));
        s_fr[tid] = make_float2(fx, fy);
    }
    __syncthreads();

    const int wlane = tid >> 5;     // warp = cell lane 0..7
    const int ct    = tid & 31;     // channel thread (float4 group within half)

    const float4* base  = (const float4*)(fm + (size_t)b * (H_ * W_ * C_))
                          + (chalf << 5) + ct;
    float4*       obase = (float4*)(out + (size_t)roi_idx * (CELLS * C_))
                          + (chalf << 5) + ct;

    // Per-thread SMEM cursors (both slots).
    char* sb_gen = s_buf + wlane * (DEPTH * SLOT_BYTES) + ct * 16;
    const uint32_t sb0 = (uint32_t)__cvta_generic_to_shared(sb_gen);

    // Lane `wlane` covers cells wlane + 8k; lane 0 additionally covers cell 48
    // (0 + 6*8), so ncells = 7 for lane 0 and 6 otherwise.
    const int ncells = (wlane == 0) ? 7 : 6;

    // Prologue: stage cell k=0 into slot 0.
    {
        const int4 off = s_off[wlane];
        cp16(sb0 + 0 * 512, base + off.x);
        cp16(sb0 + 1 * 512, base + off.y);
        cp16(sb0 + 2 * 512, base + off.z);
        cp16(sb0 + 3 * 512, base + off.w);
        asm volatile("cp.async.commit_group;");
    }

    for (int k = 0; k < ncells; k++) {
        const int cell = wlane + k * 8;

        if (k + 1 < ncells) {
            // Stage next cell into the other slot, then wait for current.
            const int4 off = s_off[cell + 8];
            const uint32_t s = sb0 + ((k + 1) & 1) * SLOT_BYTES;
            cp16(s + 0 * 512, base + off.x);
            cp16(s + 1 * 512, base + off.y);
            cp16(s + 2 * 512, base + off.z);
            cp16(s + 3 * 512, base + off.w);
            asm volatile("cp.async.commit_group;");
            asm volatile("cp.async.wait_group 1;");
        } else {
            asm volatile("cp.async.wait_group 0;");
        }

        const float2 fr = s_fr[cell];
        const char* s = sb_gen + (k & 1) * SLOT_BYTES;
        const float4 a = *(const float4*)(s + 0 * 512);
        const float4 bq = *(const float4*)(s + 1 * 512);
        const float4 c = *(const float4*)(s + 2 * 512);
        const float4 d = *(const float4*)(s + 3 * 512);

        __stcs(obase + cell * (C_ / 4), lerp4(a, bq, c, d, fr.x, fr.y));
    }
}

extern "C" void kernel_launch(void* const* d_in, const int* in_sizes, int n_in,
                              void* d_out, int out_size)
{
    const float* fm   = (const float*)d_in[0];
    const int*   rois = (const int*)d_in[1];
    float*       out  = (float*)d_out;

    roi_pool_kernel<<<B_ * R_ * 2, 256>>>(fm, rois, out);
}

// round 12
// speedup vs baseline: 1.1512x; 1.1512x over previous
#include <cuda_runtime.h>
#include <cstdint>

// Problem constants (fixed by the reference)
#define B_ 16
#define H_ 100
#define W_ 100
#define C_ 256
#define R_ 128
#define P_ 7
#define CELLS (P_ * P_)   // 49

__device__ __forceinline__ float4 lerp4(float4 a, float4 b, float4 c, float4 d,
                                        float fx, float fy)
{
    float4 o;
    float top, bot;
    top = a.x + (b.x - a.x) * fx;  bot = c.x + (d.x - c.x) * fx;  o.x = top + (bot - top) * fy;
    top = a.y + (b.y - a.y) * fx;  bot = c.y + (d.y - c.y) * fx;  o.y = top + (bot - top) * fy;
    top = a.z + (b.z - a.z) * fx;  bot = c.z + (d.z - c.z) * fx;  o.z = top + (bot - top) * fy;
    top = a.w + (b.w - a.w) * fx;  bot = c.w + (d.w - c.w) * fx;  o.w = top + (bot - top) * fy;
    return o;
}

// TWO CTAs per ROI (channel halves), grid = 4096, 224 threads = 7 warps.
// Warp w owns pooling row py=w and sweeps px=0..6 (7 cells, perfectly
// balanced). All 28 corner loads of a warp hit only TWO feature rows (y0,y1
// fixed per warp) and <=8 distinct x positions, so with L1-cached __ldg
// (.nc) a large fraction of reads are L1 re-hits instead of 250-580cyc
// L2/DRAM trips. Adjacent warps share rows too (y1[w] == y0[w+1] for small h).
// 9 CTAs/SM (2016 threads) -> ~98% theoretical occupancy at 32 regs.
// Phase 1: threads 0..48 build the per-cell bilinear table in smem.
__global__ __launch_bounds__(224, 9) void roi_pool_kernel(
    const float* __restrict__ fm,   // [B, H, W, C]
    const int*   __restrict__ rois, // [B, R, 4]  (x, y, h, w)
    float*       __restrict__ out)  // [B, R, P, P, C]
{
    __shared__ int4   s_off[CELLS];   // float4-unit offsets of the 4 corners
    __shared__ float2 s_fr[CELLS];    // (fx, fy)

    const int roi_idx = blockIdx.x >> 1;        // b*R + r
    const int chalf   = blockIdx.x & 1;         // channel half 0/1
    const int b = roi_idx >> 7;                 // R_ = 128
    const int tid = threadIdx.x;

    if (tid < CELLS) {
        const int4 roi = __ldg((const int4*)(rois + (size_t)roi_idx * 4));
        const int x = roi.x, y = roi.y, h = roi.z, w = roi.w;

        const int py = tid / P_;
        const int px = tid - py * P_;

        // y axis: src = (py+0.5)/P * h - 0.5, clipped to [0, h-1]
        const float hf = (float)h;
        float sy = ((float)py + 0.5f) * (1.0f / P_) * hf - 0.5f;
        sy = fminf(fmaxf(sy, 0.0f), hf - 1.0f);
        int   y0 = (int)floorf(sy);
        const float fy = sy - (float)y0;
        y0 += y;
        const int y1 = min(y0 + 1, y + h - 1);

        // x axis
        const float wf = (float)w;
        float sx = ((float)px + 0.5f) * (1.0f / P_) * wf - 0.5f;
        sx = fminf(fmaxf(sx, 0.0f), wf - 1.0f);
        int   x0 = (int)floorf(sx);
        const float fx = sx - (float)x0;
        x0 += x;
        const int x1 = min(x0 + 1, x + w - 1);

        // offsets in float4 units (C_/4 = 64 per pixel row)
        s_off[tid] = make_int4((y0 * W_ + x0) * (C_ / 4),
                               (y0 * W_ + x1) * (C_ / 4),
                               (y1 * W_ + x0) * (C_ / 4),
                               (y1 * W_ + x1) * (C_ / 4));
        s_fr[tid] = make_float2(fx, fy);
    }
    __syncthreads();

    const int wrp = tid >> 5;       // warp = pooling row py (0..6)
    const int ct  = tid & 31;       // channel thread (float4 group within half)

    const float4* base  = (const float4*)(fm + (size_t)b * (H_ * W_ * C_))
                          + (chalf << 5) + ct;
    float4*       obase = (float4*)(out + (size_t)roi_idx * (CELLS * C_))
                          + (chalf << 5) + ct;

    const int cell0 = wrp * P_;     // first cell of this row

    // Tuple for the first cell.
    int4   off = s_off[cell0];
    float2 fr  = s_fr[cell0];

    // Sweep px = 0..6 along the row: consecutive cells share y0/y1 rows and
    // usually one x column -> L1 re-hits.
    #pragma unroll
    for (int px = 0; px < P_; px++) {
        const int cell = cell0 + px;

        // Prefetch next tuple before touching this cell's data.
        int4   noff;
        float2 nfr;
        if (px < P_ - 1) {
            noff = s_off[cell + 1];
            nfr  = s_fr[cell + 1];
        }

        const float4 a = __ldg(base + off.x);
        const float4 bq = __ldg(base + off.y);
        const float4 c = __ldg(base + off.z);
        const float4 d = __ldg(base + off.w);

        __stcs(obase + cell * (C_ / 4), lerp4(a, bq, c, d, fr.x, fr.y));

        if (px < P_ - 1) { off = noff; fr = nfr; }
    }
}

extern "C" void kernel_launch(void* const* d_in, const int* in_sizes, int n_in,
                              void* d_out, int out_size)
{
    const float* fm   = (const float*)d_in[0];
    const int*   rois = (const int*)d_in[1];
    float*       out  = (float*)d_out;

    roi_pool_kernel<<<B_ * R_ * 2, 224>>>(fm, rois, out);
}